// round 15
// baseline (speedup 1.0000x reference)
#include <cuda_runtime.h>
#include <cstdint>

#define B_  64
#define HW_ 4096
#define C_  128      // N
#define P_  64       // K
#define NCHUNK 64
#define TILE_M 64

// smem tiles (bf16 hi/lo), pitch 72 bf16 (=36 words)
#define PITCH_W 36
#define A_TILE_W (TILE_M * PITCH_W)      // 2304 w
#define B_TILE_W (128 * PITCH_W)         // 4608 w
#define SMEM_WORDS (2 * A_TILE_W + 2 * B_TILE_W)   // 13824 w = 55296 B

// ---------------- scratch ----------------
__device__ float g_zsum[(size_t)B_ * NCHUNK * C_];   // 2 MB
__device__ float g_z2[(size_t)B_ * NCHUNK];
__device__ int   g_cnt[B_];          // zero-init; reset after use

// ---------------- helpers ----------------
__device__ __forceinline__ uint32_t bf16x2_rn(float a, float b) {
    uint32_t r;
    asm("cvt.rn.bf16x2.f32 %0, %1, %2;" : "=r"(r) : "f"(b), "f"(a));
    return r;
}
__device__ __forceinline__ void split2(float a, float b, uint32_t& h, uint32_t& l) {
    h = bf16x2_rn(a, b);
    const float fh0 = __uint_as_float(h << 16);
    const float fh1 = __uint_as_float(h & 0xFFFF0000u);
    l = bf16x2_rn(a - fh0, b - fh1);
}
__device__ __forceinline__ void mma_bf16(float* d, const uint32_t* a,
                                         uint32_t b0, uint32_t b1) {
    asm volatile(
        "mma.sync.aligned.m16n8k16.row.col.f32.bf16.bf16.f32 "
        "{%0,%1,%2,%3}, {%4,%5,%6,%7}, {%8,%9}, {%0,%1,%2,%3};"
        : "+f"(d[0]), "+f"(d[1]), "+f"(d[2]), "+f"(d[3])
        : "r"(a[0]), "r"(a[1]), "r"(a[2]), "r"(a[3]), "r"(b0), "r"(b1));
}

// ---------------- fused kernel: GEMM with z-reduce pipelined through k-loop ----------------
// grid 4096, block 256, occ 2. CTA bx: rows [bx*64, bx*64+64); z chunk (b=bx>>6, chunk=bx&63)
__global__ __launch_bounds__(256, 2)
void fused_kernel(const float* __restrict__ z, const float* __restrict__ s,
                  const float* __restrict__ kk, float* __restrict__ out,
                  float* __restrict__ dist) {
    extern __shared__ uint32_t sm[];
    uint32_t* sAh = sm;
    uint32_t* sAl = sAh + A_TILE_W;
    uint32_t* sBh = sAl + A_TILE_W;
    uint32_t* sBl = sBh + B_TILE_W;

    __shared__ float part[2][C_];
    __shared__ float zsD[C_];
    __shared__ float z2sh;
    __shared__ int   sIsLast;

    const int tid  = threadIdx.x;
    const int wid  = tid >> 5;
    const int lane = tid & 31;
    const int bx   = blockIdx.x;
    const size_t m0 = (size_t)bx * TILE_M;
    const int b     = bx >> 6;
    const int chunk = bx & 63;

    // ---- stage A (s tile): 64 rows x 16 float4 ----
    #pragma unroll
    for (int i = 0; i < 4; ++i) {
        const int idx = tid + i * 256;
        const int r = idx >> 4, q = idx & 15;
        float4 v = ((const float4*)(s + (m0 + r) * P_))[q];
        uint32_t h0, l0, h1, l1;
        split2(v.x, v.y, h0, l0);
        split2(v.z, v.w, h1, l1);
        uint32_t* ph = sAh + r * PITCH_W + q * 2;
        uint32_t* pl = sAl + r * PITCH_W + q * 2;
        ph[0] = h0; ph[1] = h1;
        pl[0] = l0; pl[1] = l1;
    }
    // ---- stage B (k): kp = lane (conflict-free STS) ----
    #pragma unroll
    for (int i = 0; i < 4; ++i) {
        const int idx = tid + i * 256;
        const int kp = idx & 31;
        const int cq = idx >> 5;
        float4 v0 = ((const float4*)(kk + (size_t)(2 * kp)     * C_))[cq];
        float4 v1 = ((const float4*)(kk + (size_t)(2 * kp + 1) * C_))[cq];
        const int n0 = cq * 4;
        uint32_t h, l;
        split2(v0.x, v1.x, h, l);
        sBh[(n0 + 0) * PITCH_W + kp] = h; sBl[(n0 + 0) * PITCH_W + kp] = l;
        split2(v0.y, v1.y, h, l);
        sBh[(n0 + 1) * PITCH_W + kp] = h; sBl[(n0 + 1) * PITCH_W + kp] = l;
        split2(v0.z, v1.z, h, l);
        sBh[(n0 + 2) * PITCH_W + kp] = h; sBl[(n0 + 2) * PITCH_W + kp] = l;
        split2(v0.w, v1.w, h, l);
        sBh[(n0 + 3) * PITCH_W + kp] = h; sBl[(n0 + 3) * PITCH_W + kp] = l;
    }

    // ---- z pipeline setup: thread covers rows rg+8j (j=0..7), col quad cq ----
    const int zcq = tid & 31;
    const int zrg = tid >> 5;
    const float4* zbase =
        (const float4*)(z + ((size_t)b * HW_ + (size_t)chunk * 64) * C_) +
        (size_t)zrg * 32 + zcq;

    float4 zacc = make_float4(0.f, 0.f, 0.f, 0.f);
    float  z2 = 0.f;
    float4 zv0 = zbase[0 * 8 * 32];      // j=0
    float4 zv1 = zbase[1 * 8 * 32];      // j=1

    __syncthreads();

    // ---- MMA phase: warp grid 2(M) x 4(N); warp tile 32x32; 4 k-steps ----
    const int warpM = wid & 1;
    const int warpN = wid >> 1;
    const int lq = lane >> 2;
    const int lr = lane & 3;

    float acc[2][4][4];
    #pragma unroll
    for (int mi = 0; mi < 2; ++mi)
        #pragma unroll
        for (int ni = 0; ni < 4; ++ni)
            #pragma unroll
            for (int j = 0; j < 4; ++j) acc[mi][ni][j] = 0.f;

    #pragma unroll
    for (int ks = 0; ks < 4; ++ks) {
        // issue next z group early (hidden under MMA)
        float4 nx0, nx1;
        if (ks < 3) {
            nx0 = zbase[(size_t)(2 * ks + 2) * 8 * 32];
            nx1 = zbase[(size_t)(2 * ks + 3) * 8 * 32];
        }

        const int kw = 8 * ks + lr;
        uint32_t ah[2][4], al[2][4];
        #pragma unroll
        for (int mi = 0; mi < 2; ++mi) {
            const int r = warpM * 32 + mi * 16 + lq;
            const uint32_t* bh = sAh + r * PITCH_W + kw;
            const uint32_t* bl = sAl + r * PITCH_W + kw;
            ah[mi][0] = bh[0];
            ah[mi][1] = bh[8 * PITCH_W];
            ah[mi][2] = bh[4];
            ah[mi][3] = bh[8 * PITCH_W + 4];
            al[mi][0] = bl[0];
            al[mi][1] = bl[8 * PITCH_W];
            al[mi][2] = bl[4];
            al[mi][3] = bl[8 * PITCH_W + 4];
        }
        #pragma unroll
        for (int ni = 0; ni < 4; ++ni) {
            const int n = warpN * 32 + ni * 8 + lq;
            const uint32_t* bh = sBh + n * PITCH_W + kw;
            const uint32_t* bl = sBl + n * PITCH_W + kw;
            const uint32_t bh0 = bh[0], bh1 = bh[4];
            const uint32_t bl0 = bl[0], bl1 = bl[4];
            #pragma unroll
            for (int mi = 0; mi < 2; ++mi) {
                mma_bf16(acc[mi][ni], ah[mi], bh0, bh1);
                mma_bf16(acc[mi][ni], ah[mi], bl0, bl1);
                mma_bf16(acc[mi][ni], al[mi], bh0, bh1);
            }
        }

        // consume current z group
        zacc.x += zv0.x; zacc.y += zv0.y; zacc.z += zv0.z; zacc.w += zv0.w;
        z2 += zv0.x * zv0.x + zv0.y * zv0.y + zv0.z * zv0.z + zv0.w * zv0.w;
        zacc.x += zv1.x; zacc.y += zv1.y; zacc.z += zv1.z; zacc.w += zv1.w;
        z2 += zv1.x * zv1.x + zv1.y * zv1.y + zv1.z * zv1.z + zv1.w * zv1.w;
        zv0 = nx0; zv1 = nx1;
    }

    // ---- epilogue: out stores ----
    #pragma unroll
    for (int mi = 0; mi < 2; ++mi) {
        const size_t row = m0 + warpM * 32 + mi * 16 + lq;
        #pragma unroll
        for (int ni = 0; ni < 4; ++ni) {
            const int col = warpN * 32 + ni * 8 + 2 * lr;
            *(float2*)(out + row * C_ + col) =
                make_float2(acc[mi][ni][0], acc[mi][ni][1]);
            *(float2*)(out + (row + 8) * C_ + col) =
                make_float2(acc[mi][ni][2], acc[mi][ni][3]);
        }
    }

    // ---- z cross-thread reduction (reuse dynamic smem) ----
    __syncthreads();                       // all frag reads done; smem reusable
    float4* sred = (float4*)sm;            // [256]
    float*  sz2w = (float*)(sred + 256);   // [8]
    #pragma unroll
    for (int off = 16; off > 0; off >>= 1)
        z2 += __shfl_down_sync(0xffffffffu, z2, off);
    sred[tid] = zacc;
    if (lane == 0) sz2w[wid] = z2;
    __syncthreads();

    if (zrg == 0) {
        float4 t = sred[zcq];
        #pragma unroll
        for (int g = 1; g < 8; ++g) {
            float4 v = sred[g * 32 + zcq];
            t.x += v.x; t.y += v.y; t.z += v.z; t.w += v.w;
        }
        ((float4*)(g_zsum + ((size_t)b * NCHUNK + chunk) * C_))[zcq] = t;
        if (zcq == 0) {
            float tt = 0.f;
            #pragma unroll
            for (int g = 0; g < 8; ++g) tt += sz2w[g];
            g_z2[(size_t)b * NCHUNK + chunk] = tt;
        }
    }

    // ---- completion counter; last CTA of batch computes dist row ----
    __threadfence();
    __syncthreads();
    if (tid == 0) {
        const int old = atomicAdd(&g_cnt[b], 1);
        sIsLast = (old == NCHUNK - 1);
    }
    __syncthreads();

    if (sIsLast) {
        __threadfence();
        {
            const int c    = tid & 127;
            const int half = tid >> 7;
            const float* basez =
                g_zsum + ((size_t)b * NCHUNK + half * 32) * C_ + c;
            float a = 0.f;
            #pragma unroll
            for (int ch = 0; ch < 32; ++ch) a += basez[(size_t)ch * C_];
            part[half][c] = a;
        }
        if (tid < 32) {
            float t = g_z2[(size_t)b * NCHUNK + tid] +
                      g_z2[(size_t)b * NCHUNK + 32 + tid];
            #pragma unroll
            for (int off = 16; off > 0; off >>= 1)
                t += __shfl_down_sync(0xffffffffu, t, off);
            if (tid == 0) z2sh = t;
        }
        __syncthreads();
        if (tid < C_) zsD[tid] = part[0][tid] + part[1][tid];
        __syncthreads();

        {
            const int p   = tid >> 2;
            const int sub = tid & 3;
            const float* kp = kk + (size_t)p * C_ + sub * 32;
            const float* zp = zsD + sub * 32;
            float dot = 0.f, k2 = 0.f;
            #pragma unroll
            for (int c = 0; c < 32; ++c) {
                const float kv = kp[c];
                dot += zp[c] * kv;
                k2  += kv * kv;
            }
            dot += __shfl_xor_sync(0xffffffffu, dot, 1);
            k2  += __shfl_xor_sync(0xffffffffu, k2, 1);
            dot += __shfl_xor_sync(0xffffffffu, dot, 2);
            k2  += __shfl_xor_sync(0xffffffffu, k2, 2);
            if (sub == 0)
                dist[(size_t)b * P_ + p] = z2sh - 2.f * dot + (float)HW_ * k2;
        }
        if (tid == 0) g_cnt[b] = 0;   // reset for next graph replay
    }
}

// ---------------- launch ----------------
extern "C" void kernel_launch(void* const* d_in, const int* in_sizes, int n_in,
                              void* d_out, int out_size) {
    const float* z = (const float*)d_in[0];
    const float* s = (const float*)d_in[1];
    const float* k = (const float*)d_in[2];
    float* out  = (float*)d_out;
    float* dist = out + (size_t)in_sizes[0];

    static bool attr_set = false;
    if (!attr_set) {
        cudaFuncSetAttribute(fused_kernel,
                             cudaFuncAttributeMaxDynamicSharedMemorySize,
                             SMEM_WORDS * (int)sizeof(uint32_t));
        attr_set = true;
    }

    fused_kernel<<<(B_ * HW_) / TILE_M, 256, SMEM_WORDS * sizeof(uint32_t)>>>(
        z, s, k, out, dist);
}

// round 16
// speedup vs baseline: 1.3232x; 1.3232x over previous
#include <cuda_runtime.h>
#include <cstdint>

#define B_  64
#define HW_ 4096
#define C_  128      // N
#define P_  64       // K
#define NCHUNK 32
#define TILE_M 128

// smem tiles (bf16 hi/lo), pitch 72 bf16 (=36 words)
#define PITCH_W 36
#define A_TILE_W (128 * PITCH_W)
#define B_TILE_W (128 * PITCH_W)
#define SMEM_WORDS (2 * A_TILE_W + 2 * B_TILE_W)   // 73728 bytes

// ---------------- scratch ----------------
__device__ float g_zsum[(size_t)B_ * NCHUNK * C_];
__device__ float g_z2[(size_t)B_ * NCHUNK];
__device__ int   g_cnt[B_];          // zero-init; reset after use

// ---------------- helpers ----------------
__device__ __forceinline__ uint32_t bf16x2_rn(float a, float b) {
    uint32_t r;
    asm("cvt.rn.bf16x2.f32 %0, %1, %2;" : "=r"(r) : "f"(b), "f"(a));
    return r;
}
__device__ __forceinline__ void split2(float a, float b, uint32_t& h, uint32_t& l) {
    h = bf16x2_rn(a, b);
    const float fh0 = __uint_as_float(h << 16);
    const float fh1 = __uint_as_float(h & 0xFFFF0000u);
    l = bf16x2_rn(a - fh0, b - fh1);
}
__device__ __forceinline__ void mma_bf16(float* d, const uint32_t* a,
                                         uint32_t b0, uint32_t b1) {
    asm volatile(
        "mma.sync.aligned.m16n8k16.row.col.f32.bf16.bf16.f32 "
        "{%0,%1,%2,%3}, {%4,%5,%6,%7}, {%8,%9}, {%0,%1,%2,%3};"
        : "+f"(d[0]), "+f"(d[1]), "+f"(d[2]), "+f"(d[3])
        : "r"(a[0]), "r"(a[1]), "r"(a[2]), "r"(a[3]), "r"(b0), "r"(b1));
}

// ---------------- fused kernel: z-reduce + 3xBF16 GEMM + dist tail ----------------
// grid 2048, block 256 (8 warps), occ 2.
__global__ __launch_bounds__(256, 2)
void fused_kernel(const float* __restrict__ z, const float* __restrict__ s,
                  const float* __restrict__ kk, float* __restrict__ out,
                  float* __restrict__ dist) {
    extern __shared__ uint32_t sm[];
    uint32_t* sAh = sm;                    // [128 m][36 w]  A hi
    uint32_t* sAl = sAh + A_TILE_W;        // A lo
    uint32_t* sBh = sAl + A_TILE_W;        // [128 n][36 w]  B hi
    uint32_t* sBl = sBh + B_TILE_W;        // B lo

    __shared__ float4 sred[256];
    __shared__ float  sz2[8];
    __shared__ float  part[2][C_];
    __shared__ float  zsD[C_];
    __shared__ float  z2sh;
    __shared__ int    sIsLast;

    const int tid  = threadIdx.x;
    const int wid  = tid >> 5;
    const int lane = tid & 31;
    const int bx   = blockIdx.x;
    const size_t m0 = (size_t)bx * TILE_M;
    const int b     = bx >> 5;
    const int chunk = bx & 31;

    // ---- stage A (s tile): [m][k], k-contiguous ----
    #pragma unroll
    for (int i = 0; i < 8; ++i) {
        const int idx = tid + i * 256;          // 0..2047 float4
        const int r = idx >> 4, q = idx & 15;
        float4 v = ((const float4*)(s + (m0 + r) * P_))[q];
        uint32_t h0, l0, h1, l1;
        split2(v.x, v.y, h0, l0);
        split2(v.z, v.w, h1, l1);
        uint32_t* ph = sAh + r * PITCH_W + q * 2;
        uint32_t* pl = sAl + r * PITCH_W + q * 2;
        ph[0] = h0; ph[1] = h1;
        pl[0] = l0; pl[1] = l1;
    }
    // ---- stage B (k): kp = lane (conflict-free STS; k is L1/L2-hot) ----
    #pragma unroll
    for (int i = 0; i < 4; ++i) {
        const int idx = tid + i * 256;          // 0..1023
        const int kp = idx & 31;                // == lane
        const int cq = idx >> 5;                // const per warp
        float4 v0 = ((const float4*)(kk + (size_t)(2 * kp)     * C_))[cq];
        float4 v1 = ((const float4*)(kk + (size_t)(2 * kp + 1) * C_))[cq];
        const int n0 = cq * 4;
        uint32_t h, l;
        split2(v0.x, v1.x, h, l);
        sBh[(n0 + 0) * PITCH_W + kp] = h; sBl[(n0 + 0) * PITCH_W + kp] = l;
        split2(v0.y, v1.y, h, l);
        sBh[(n0 + 1) * PITCH_W + kp] = h; sBl[(n0 + 1) * PITCH_W + kp] = l;
        split2(v0.z, v1.z, h, l);
        sBh[(n0 + 2) * PITCH_W + kp] = h; sBl[(n0 + 2) * PITCH_W + kp] = l;
        split2(v0.w, v1.w, h, l);
        sBh[(n0 + 3) * PITCH_W + kp] = h; sBl[(n0 + 3) * PITCH_W + kp] = l;
    }

    // ---- z reduction phase ----
    {
        const float4* base =
            (const float4*)(z + ((size_t)b * HW_ + (size_t)chunk * 128) * C_);
        const int cq = tid & 31;
        const int rg = tid >> 5;

        float4 acc = make_float4(0.f, 0.f, 0.f, 0.f);
        float z2 = 0.f;
        #pragma unroll
        for (int j = 0; j < 16; ++j) {
            float4 v = base[(size_t)(rg + 8 * j) * (C_ / 4) + cq];
            acc.x += v.x; acc.y += v.y; acc.z += v.z; acc.w += v.w;
            z2 += v.x * v.x + v.y * v.y + v.z * v.z + v.w * v.w;
        }
        #pragma unroll
        for (int off = 16; off > 0; off >>= 1)
            z2 += __shfl_down_sync(0xffffffffu, z2, off);
        sred[tid] = acc;
        if (cq == 0) sz2[rg] = z2;
        __syncthreads();

        if (rg == 0) {
            float4 t = sred[cq];
            #pragma unroll
            for (int g = 1; g < 8; ++g) {
                float4 v = sred[g * 32 + cq];
                t.x += v.x; t.y += v.y; t.z += v.z; t.w += v.w;
            }
            ((float4*)(g_zsum + ((size_t)b * NCHUNK + chunk) * C_))[cq] = t;
            if (cq == 0) {
                float tt = 0.f;
                #pragma unroll
                for (int g = 0; g < 8; ++g) tt += sz2[g];
                g_z2[(size_t)b * NCHUNK + chunk] = tt;
            }
            __threadfence();   // publish z partials before the counter bump
        }
    }
    __syncthreads();

    // ---- completion counter (hoisted before MMA: z data is final here) ----
    if (tid == 0) {
        const int old = atomicAdd(&g_cnt[b], 1);
        sIsLast = (old == NCHUNK - 1);
    }

    // ---- MMA phase: warp grid 4(M) x 2(N); warp tile 32x64; 4 k-steps ----
    const int warpM = wid & 3;
    const int warpN = wid >> 2;
    const int lq = lane >> 2;   // 0..7
    const int lr = lane & 3;    // 0..3

    float acc[2][8][4];
    #pragma unroll
    for (int mi = 0; mi < 2; ++mi)
        #pragma unroll
        for (int ni = 0; ni < 8; ++ni)
            #pragma unroll
            for (int j = 0; j < 4; ++j) acc[mi][ni][j] = 0.f;

    #pragma unroll
    for (int ks = 0; ks < 4; ++ks) {
        const int kw = 8 * ks + lr;
        uint32_t ah[2][4], al[2][4];
        #pragma unroll
        for (int mi = 0; mi < 2; ++mi) {
            const int r = warpM * 32 + mi * 16 + lq;
            const uint32_t* bh = sAh + r * PITCH_W + kw;
            const uint32_t* bl = sAl + r * PITCH_W + kw;
            ah[mi][0] = bh[0];
            ah[mi][1] = bh[8 * PITCH_W];
            ah[mi][2] = bh[4];
            ah[mi][3] = bh[8 * PITCH_W + 4];
            al[mi][0] = bl[0];
            al[mi][1] = bl[8 * PITCH_W];
            al[mi][2] = bl[4];
            al[mi][3] = bl[8 * PITCH_W + 4];
        }
        #pragma unroll
        for (int ni = 0; ni < 8; ++ni) {
            const int n = warpN * 64 + ni * 8 + lq;
            const uint32_t* bh = sBh + n * PITCH_W + kw;
            const uint32_t* bl = sBl + n * PITCH_W + kw;
            const uint32_t bh0 = bh[0], bh1 = bh[4];
            const uint32_t bl0 = bl[0], bl1 = bl[4];
            #pragma unroll
            for (int mi = 0; mi < 2; ++mi) {
                mma_bf16(acc[mi][ni], ah[mi], bh0, bh1);  // hi*hi
                mma_bf16(acc[mi][ni], ah[mi], bl0, bl1);  // hi*lo
                mma_bf16(acc[mi][ni], al[mi], bh0, bh1);  // lo*hi
            }
        }
    }

    // ---- epilogue ----
    #pragma unroll
    for (int mi = 0; mi < 2; ++mi) {
        const size_t row = m0 + warpM * 32 + mi * 16 + lq;
        #pragma unroll
        for (int ni = 0; ni < 8; ++ni) {
            const int col = warpN * 64 + ni * 8 + 2 * lr;
            *(float2*)(out + row * C_ + col) =
                make_float2(acc[mi][ni][0], acc[mi][ni][1]);
            *(float2*)(out + (row + 8) * C_ + col) =
                make_float2(acc[mi][ni][2], acc[mi][ni][3]);
        }
    }

    // ---- dist tail: last CTA of each batch (cold path, once per 32 CTAs) ----
    __syncthreads();
    if (sIsLast) {
        __threadfence();
        {
            const int c    = tid & 127;
            const int half = tid >> 7;
            const float* basez =
                g_zsum + ((size_t)b * NCHUNK + half * 16) * C_ + c;
            float a = 0.f;
            #pragma unroll
            for (int ch = 0; ch < 16; ++ch) a += basez[(size_t)ch * C_];
            part[half][c] = a;
        }
        if (tid < 32) {
            float t = g_z2[(size_t)b * NCHUNK + tid];
            #pragma unroll
            for (int off = 16; off > 0; off >>= 1)
                t += __shfl_down_sync(0xffffffffu, t, off);
            if (tid == 0) z2sh = t;
        }
        __syncthreads();
        if (tid < C_) zsD[tid] = part[0][tid] + part[1][tid];
        __syncthreads();

        {
            const int p   = tid >> 2;
            const int sub = tid & 3;
            const float* kp = kk + (size_t)p * C_ + sub * 32;
            const float* zp = zsD + sub * 32;
            float dot = 0.f, k2 = 0.f;
            #pragma unroll
            for (int c = 0; c < 32; ++c) {
                const float kv = kp[c];
                dot += zp[c] * kv;
                k2  += kv * kv;
            }
            dot += __shfl_xor_sync(0xffffffffu, dot, 1);
            k2  += __shfl_xor_sync(0xffffffffu, k2, 1);
            dot += __shfl_xor_sync(0xffffffffu, dot, 2);
            k2  += __shfl_xor_sync(0xffffffffu, k2, 2);
            if (sub == 0)
                dist[(size_t)b * P_ + p] = z2sh - 2.f * dot + (float)HW_ * k2;
        }
        if (tid == 0) g_cnt[b] = 0;   // reset for next graph replay
    }
}

// ---------------- launch ----------------
extern "C" void kernel_launch(void* const* d_in, const int* in_sizes, int n_in,
                              void* d_out, int out_size) {
    const float* z = (const float*)d_in[0];
    const float* s = (const float*)d_in[1];
    const float* k = (const float*)d_in[2];
    float* out  = (float*)d_out;
    float* dist = out + (size_t)in_sizes[0];

    static bool attr_set = false;
    if (!attr_set) {
        cudaFuncSetAttribute(fused_kernel,
                             cudaFuncAttributeMaxDynamicSharedMemorySize,
                             SMEM_WORDS * (int)sizeof(uint32_t));
        attr_set = true;
    }

    fused_kernel<<<(B_ * HW_) / TILE_M, 256, SMEM_WORDS * sizeof(uint32_t)>>>(
        z, s, k, out, dist);
}

// round 17
// speedup vs baseline: 1.3301x; 1.0052x over previous
#include <cuda_runtime.h>
#include <cstdint>

#define B_  64
#define HW_ 4096
#define C_  128      // N
#define P_  64       // K
#define NCHUNK 32
#define TILE_M 128

// smem tiles (bf16 hi/lo), pitch 72 bf16 (=36 words)
#define PITCH_W 36
#define A_TILE_W (128 * PITCH_W)
#define B_TILE_W (128 * PITCH_W)
#define SMEM_WORDS (2 * A_TILE_W + 2 * B_TILE_W)   // 73728 bytes

// ---------------- scratch ----------------
__device__ float g_zsum[(size_t)B_ * NCHUNK * C_];
__device__ float g_z2[(size_t)B_ * NCHUNK];
__device__ int   g_cnt[B_];          // zero-init; reset after use

// ---------------- helpers ----------------
__device__ __forceinline__ uint32_t bf16x2_rn(float a, float b) {
    uint32_t r;
    asm("cvt.rn.bf16x2.f32 %0, %1, %2;" : "=r"(r) : "f"(b), "f"(a));
    return r;
}
__device__ __forceinline__ void split2(float a, float b, uint32_t& h, uint32_t& l) {
    h = bf16x2_rn(a, b);
    const float fh0 = __uint_as_float(h << 16);
    const float fh1 = __uint_as_float(h & 0xFFFF0000u);
    l = bf16x2_rn(a - fh0, b - fh1);
}
__device__ __forceinline__ void mma_bf16(float* d, const uint32_t* a,
                                         uint32_t b0, uint32_t b1) {
    asm volatile(
        "mma.sync.aligned.m16n8k16.row.col.f32.bf16.bf16.f32 "
        "{%0,%1,%2,%3}, {%4,%5,%6,%7}, {%8,%9}, {%0,%1,%2,%3};"
        : "+f"(d[0]), "+f"(d[1]), "+f"(d[2]), "+f"(d[3])
        : "r"(a[0]), "r"(a[1]), "r"(a[2]), "r"(a[3]), "r"(b0), "r"(b1));
}
__device__ __forceinline__ void ldsm_x4(uint32_t addr, uint32_t* r) {
    asm volatile("ldmatrix.sync.aligned.m8n8.x4.shared.b16 {%0,%1,%2,%3}, [%4];"
        : "=r"(r[0]), "=r"(r[1]), "=r"(r[2]), "=r"(r[3]) : "r"(addr));
}

// ---------------- fused kernel: z-reduce + 3xBF16 GEMM (ldmatrix) + dist tail ----------------
__global__ __launch_bounds__(256, 2)
void fused_kernel(const float* __restrict__ z, const float* __restrict__ s,
                  const float* __restrict__ kk, float* __restrict__ out,
                  float* __restrict__ dist) {
    extern __shared__ uint32_t sm[];
    uint32_t* sAh = sm;                    // [128 m][36 w]  A hi
    uint32_t* sAl = sAh + A_TILE_W;        // A lo
    uint32_t* sBh = sAl + A_TILE_W;        // [128 n][36 w]  B hi
    uint32_t* sBl = sBh + B_TILE_W;        // B lo

    __shared__ float4 sred[256];
    __shared__ float  sz2[8];
    __shared__ float  part[2][C_];
    __shared__ float  zsD[C_];
    __shared__ float  z2sh;
    __shared__ int    sIsLast;

    const int tid  = threadIdx.x;
    const int wid  = tid >> 5;
    const int lane = tid & 31;
    const int bx   = blockIdx.x;
    const size_t m0 = (size_t)bx * TILE_M;
    const int b     = bx >> 5;
    const int chunk = bx & 31;

    // ---- stage A (s tile): [m][k], k-contiguous ----
    #pragma unroll
    for (int i = 0; i < 8; ++i) {
        const int idx = tid + i * 256;          // 0..2047 float4
        const int r = idx >> 4, q = idx & 15;
        float4 v = ((const float4*)(s + (m0 + r) * P_))[q];
        uint32_t h0, l0, h1, l1;
        split2(v.x, v.y, h0, l0);
        split2(v.z, v.w, h1, l1);
        uint32_t* ph = sAh + r * PITCH_W + q * 2;
        uint32_t* pl = sAl + r * PITCH_W + q * 2;
        ph[0] = h0; ph[1] = h1;
        pl[0] = l0; pl[1] = l1;
    }
    // ---- stage B (k): kp = lane (conflict-free STS; k is L1/L2-hot) ----
    #pragma unroll
    for (int i = 0; i < 4; ++i) {
        const int idx = tid + i * 256;          // 0..1023
        const int kp = idx & 31;                // == lane
        const int cq = idx >> 5;                // const per warp
        float4 v0 = ((const float4*)(kk + (size_t)(2 * kp)     * C_))[cq];
        float4 v1 = ((const float4*)(kk + (size_t)(2 * kp + 1) * C_))[cq];
        const int n0 = cq * 4;
        uint32_t h, l;
        split2(v0.x, v1.x, h, l);
        sBh[(n0 + 0) * PITCH_W + kp] = h; sBl[(n0 + 0) * PITCH_W + kp] = l;
        split2(v0.y, v1.y, h, l);
        sBh[(n0 + 1) * PITCH_W + kp] = h; sBl[(n0 + 1) * PITCH_W + kp] = l;
        split2(v0.z, v1.z, h, l);
        sBh[(n0 + 2) * PITCH_W + kp] = h; sBl[(n0 + 2) * PITCH_W + kp] = l;
        split2(v0.w, v1.w, h, l);
        sBh[(n0 + 3) * PITCH_W + kp] = h; sBl[(n0 + 3) * PITCH_W + kp] = l;
    }

    // ---- z reduction phase ----
    {
        const float4* base =
            (const float4*)(z + ((size_t)b * HW_ + (size_t)chunk * 128) * C_);
        const int cq = tid & 31;
        const int rg = tid >> 5;

        float4 acc = make_float4(0.f, 0.f, 0.f, 0.f);
        float z2 = 0.f;
        #pragma unroll
        for (int j = 0; j < 16; ++j) {
            float4 v = base[(size_t)(rg + 8 * j) * (C_ / 4) + cq];
            acc.x += v.x; acc.y += v.y; acc.z += v.z; acc.w += v.w;
            z2 += v.x * v.x + v.y * v.y + v.z * v.z + v.w * v.w;
        }
        #pragma unroll
        for (int off = 16; off > 0; off >>= 1)
            z2 += __shfl_down_sync(0xffffffffu, z2, off);
        sred[tid] = acc;
        if (cq == 0) sz2[rg] = z2;
        __syncthreads();

        if (rg == 0) {
            float4 t = sred[cq];
            #pragma unroll
            for (int g = 1; g < 8; ++g) {
                float4 v = sred[g * 32 + cq];
                t.x += v.x; t.y += v.y; t.z += v.z; t.w += v.w;
            }
            ((float4*)(g_zsum + ((size_t)b * NCHUNK + chunk) * C_))[cq] = t;
            if (cq == 0) {
                float tt = 0.f;
                #pragma unroll
                for (int g = 0; g < 8; ++g) tt += sz2[g];
                g_z2[(size_t)b * NCHUNK + chunk] = tt;
            }
            __threadfence();   // publish z partials before the counter bump
        }
    }
    __syncthreads();

    // ---- completion counter (z data final here) ----
    if (tid == 0) {
        const int old = atomicAdd(&g_cnt[b], 1);
        sIsLast = (old == NCHUNK - 1);
    }

    // ---- MMA phase (ldmatrix): warp grid 4(M) x 2(N); warp tile 32x64 ----
    const int warpM = wid & 3;
    const int warpN = wid >> 2;
    const int lq = lane >> 2;   // 0..7 (epilogue)
    const int lr = lane & 3;    // 0..3 (epilogue)

    // ldmatrix lane->row mapping (A and B identical pattern)
    const int laneRow = ((lane >> 3) & 1) * 8 + (lane & 7);   // row within 16
    const int kHiA    = (lane >> 4) * 4;                      // +4 words for k8-15
    const int nOffB   = ((lane >> 4) & 1) * 8 + (lane & 7);   // n row within 16
    const int kHiB    = ((lane >> 3) & 1) * 4;

    uint32_t aAddrH[2], aAddrL[2], bAddrH[4], bAddrL[4];
    #pragma unroll
    for (int mi = 0; mi < 2; ++mi) {
        const int r = warpM * 32 + mi * 16 + laneRow;
        aAddrH[mi] = (uint32_t)__cvta_generic_to_shared(sAh + r * PITCH_W + kHiA);
        aAddrL[mi] = (uint32_t)__cvta_generic_to_shared(sAl + r * PITCH_W + kHiA);
    }
    #pragma unroll
    for (int j = 0; j < 4; ++j) {
        const int n = warpN * 64 + 16 * j + nOffB;
        bAddrH[j] = (uint32_t)__cvta_generic_to_shared(sBh + n * PITCH_W + kHiB);
        bAddrL[j] = (uint32_t)__cvta_generic_to_shared(sBl + n * PITCH_W + kHiB);
    }

    float acc[2][8][4];
    #pragma unroll
    for (int mi = 0; mi < 2; ++mi)
        #pragma unroll
        for (int ni = 0; ni < 8; ++ni)
            #pragma unroll
            for (int j = 0; j < 4; ++j) acc[mi][ni][j] = 0.f;

    #pragma unroll
    for (int ks = 0; ks < 4; ++ks) {
        const uint32_t ko = ks * 32;   // 8 words = 32 bytes per k-step
        uint32_t ah[2][4], al[2][4];
        ldsm_x4(aAddrH[0] + ko, ah[0]);
        ldsm_x4(aAddrH[1] + ko, ah[1]);
        ldsm_x4(aAddrL[0] + ko, al[0]);
        ldsm_x4(aAddrL[1] + ko, al[1]);
        #pragma unroll
        for (int j = 0; j < 4; ++j) {
            uint32_t bh[4], bl[4];
            ldsm_x4(bAddrH[j] + ko, bh);
            ldsm_x4(bAddrL[j] + ko, bl);
            #pragma unroll
            for (int t = 0; t < 2; ++t) {
                const int ni = 2 * j + t;
                const uint32_t bh0 = bh[2 * t], bh1 = bh[2 * t + 1];
                const uint32_t bl0 = bl[2 * t], bl1 = bl[2 * t + 1];
                #pragma unroll
                for (int mi = 0; mi < 2; ++mi) {
                    mma_bf16(acc[mi][ni], ah[mi], bh0, bh1);  // hi*hi
                    mma_bf16(acc[mi][ni], ah[mi], bl0, bl1);  // hi*lo
                    mma_bf16(acc[mi][ni], al[mi], bh0, bh1);  // lo*hi
                }
            }
        }
    }

    // ---- epilogue ----
    #pragma unroll
    for (int mi = 0; mi < 2; ++mi) {
        const size_t row = m0 + warpM * 32 + mi * 16 + lq;
        #pragma unroll
        for (int ni = 0; ni < 8; ++ni) {
            const int col = warpN * 64 + ni * 8 + 2 * lr;
            *(float2*)(out + row * C_ + col) =
                make_float2(acc[mi][ni][0], acc[mi][ni][1]);
            *(float2*)(out + (row + 8) * C_ + col) =
                make_float2(acc[mi][ni][2], acc[mi][ni][3]);
        }
    }

    // ---- dist tail: last CTA of each batch ----
    __syncthreads();
    if (sIsLast) {
        __threadfence();
        {
            const int c    = tid & 127;
            const int half = tid >> 7;
            const float* basez =
                g_zsum + ((size_t)b * NCHUNK + half * 16) * C_ + c;
            float a = 0.f;
            #pragma unroll
            for (int ch = 0; ch < 16; ++ch) a += basez[(size_t)ch * C_];
            part[half][c] = a;
        }
        if (tid < 32) {
            float t = g_z2[(size_t)b * NCHUNK + tid];
            #pragma unroll
            for (int off = 16; off > 0; off >>= 1)
                t += __shfl_down_sync(0xffffffffu, t, off);
            if (tid == 0) z2sh = t;
        }
        __syncthreads();
        if (tid < C_) zsD[tid] = part[0][tid] + part[1][tid];
        __syncthreads();

        {
            const int p   = tid >> 2;
            const int sub = tid & 3;
            const float* kp = kk + (size_t)p * C_ + sub * 32;
            const float* zp = zsD + sub * 32;
            float dot = 0.f, k2 = 0.f;
            #pragma unroll
            for (int c = 0; c < 32; ++c) {
                const float kv = kp[c];
                dot += zp[c] * kv;
                k2  += kv * kv;
            }
            dot += __shfl_xor_sync(0xffffffffu, dot, 1);
            k2  += __shfl_xor_sync(0xffffffffu, k2, 1);
            dot += __shfl_xor_sync(0xffffffffu, dot, 2);
            k2  += __shfl_xor_sync(0xffffffffu, k2, 2);
            if (sub == 0)
                dist[(size_t)b * P_ + p] = z2sh - 2.f * dot + (float)HW_ * k2;
        }
        if (tid == 0) g_cnt[b] = 0;   // reset for next graph replay
    }
}

// ---------------- launch ----------------
extern "C" void kernel_launch(void* const* d_in, const int* in_sizes, int n_in,
                              void* d_out, int out_size) {
    const float* z = (const float*)d_in[0];
    const float* s = (const float*)d_in[1];
    const float* k = (const float*)d_in[2];
    float* out  = (float*)d_out;
    float* dist = out + (size_t)in_sizes[0];

    static bool attr_set = false;
    if (!attr_set) {
        cudaFuncSetAttribute(fused_kernel,
                             cudaFuncAttributeMaxDynamicSharedMemorySize,
                             SMEM_WORDS * (int)sizeof(uint32_t));
        attr_set = true;
    }

    fused_kernel<<<(B_ * HW_) / TILE_M, 256, SMEM_WORDS * sizeof(uint32_t)>>>(
        z, s, k, out, dist);
}